// round 9
// baseline (speedup 1.0000x reference)
#include <cuda_runtime.h>
#include <cuda_bf16.h>
#include <cstdint>

#define LOG2E 1.4426950408889634f
#define C1 (0.17677669529663687f * LOG2E)   // sm_scale * log2(e)

// smem layout (bytes) — R4 padded layout
#define OFF_MS 0                      // mask * log2e, 256 f32 (1024 B)
#define OFF_KH 1024                   // K hi bf16 [256][32], row stride 80 B
#define OFF_KL (OFF_KH + 256*80)      // K lo
#define OFF_VH (OFF_KL + 256*80)      // Vt hi bf16 [32][256], row stride 528 B
#define OFF_VL (OFF_VH + 32*528)      // Vt lo
#define SMEM_TOTAL (OFF_VL + 32*528)  // 75776 B

__device__ __forceinline__ float ex2f(float x) {
    float y; asm("ex2.approx.ftz.f32 %0, %1;" : "=f"(y) : "f"(x)); return y;
}
__device__ __forceinline__ uint32_t pack2(float a, float b) {
    __nv_bfloat162 t = __floats2bfloat162_rn(a, b);   // low half = a
    return *(uint32_t*)&t;
}
__device__ __forceinline__ void split2(float2 x, uint32_t& hi, uint32_t& lo) {
    __nv_bfloat162 hv = __floats2bfloat162_rn(x.x, x.y);
    float2 hf = __bfloat1622float2(hv);
    hi = *(uint32_t*)&hv;
    lo = pack2(x.x - hf.x, x.y - hf.y);
}
__device__ __forceinline__ void mma16816(float* d, const uint32_t* a,
                                         uint32_t b0, uint32_t b1) {
    asm volatile(
        "mma.sync.aligned.m16n8k16.row.col.f32.bf16.bf16.f32 "
        "{%0,%1,%2,%3}, {%4,%5,%6,%7}, {%8,%9}, {%0,%1,%2,%3};"
        : "+f"(d[0]), "+f"(d[1]), "+f"(d[2]), "+f"(d[3])
        : "r"(a[0]), "r"(a[1]), "r"(a[2]), "r"(a[3]), "r"(b0), "r"(b1));
}

__global__ __launch_bounds__(256, 2)
void TFA_88089779241014_kernel(const float* __restrict__ q,
                               const float* __restrict__ k,
                               const float* __restrict__ v,
                               const float* __restrict__ mask,
                               const float* __restrict__ tri,
                               float* __restrict__ out) {
    extern __shared__ char smem[];

    const int tid  = threadIdx.x;
    const int lane = tid & 31;
    const int wid  = tid >> 5;
    const int g    = lane >> 2;
    const int c    = (lane & 3) * 2;
    const int tg   = lane & 3;

    const int bx   = blockIdx.x;        // head*2 + mtile
    const int head = bx >> 1;           // n*4 + h
    const int mt   = bx & 1;
    const int n    = head >> 2;
    const int h    = head & 3;

    const float* kb = k + (size_t)head * 8192;
    const float* vb = v + (size_t)head * 8192;
    const float* mb = mask + (size_t)n * 256;

    // ---- stage K as bf16 hi/lo, [t][d] rows, 80B stride ----
    for (int i = tid; i < 4096; i += 256) {
        int t = i >> 4, c2 = (i & 15) << 1;
        float2 x = *(const float2*)(kb + t * 32 + c2);
        uint32_t hi, lo; split2(x, hi, lo);
        *(uint32_t*)(smem + OFF_KH + t * 80 + c2 * 2) = hi;
        *(uint32_t*)(smem + OFF_KL + t * 80 + c2 * 2) = lo;
    }
    // ---- stage V transposed: Vt[d][t], 528B stride ----
    for (int i = tid; i < 2048; i += 256) {
        float4 x = ((const float4*)vb)[i];
        int t = i >> 3, d4 = (i & 7) << 2;
        float e[4] = {x.x, x.y, x.z, x.w};
        #pragma unroll
        for (int j = 0; j < 4; j++) {
            int d = d4 + j;
            __nv_bfloat16 hv = __float2bfloat16_rn(e[j]);
            __nv_bfloat16 lv = __float2bfloat16_rn(e[j] - __bfloat162float(hv));
            *(__nv_bfloat16*)(smem + OFF_VH + d * 528 + t * 2) = hv;
            *(__nv_bfloat16*)(smem + OFF_VL + d * 528 + t * 2) = lv;
        }
    }
    for (int i = tid; i < 256; i += 256)
        *(float*)(smem + OFF_MS + i * 4) = mb[i] * LOG2E;

    // ---- Q fragments (registers, whole kernel) ----
    const int rowbase = mt * 128 + wid * 16;
    const float* qrow = q + (size_t)head * 8192 + (size_t)rowbase * 32;
    uint32_t qhi[2][4], qlo[2][4];
    #pragma unroll
    for (int s = 0; s < 2; s++) {
        int k0 = s * 16;
        split2(*(const float2*)(qrow + (g)     * 32 + k0 + c),     qhi[s][0], qlo[s][0]);
        split2(*(const float2*)(qrow + (g + 8) * 32 + k0 + c),     qhi[s][1], qlo[s][1]);
        split2(*(const float2*)(qrow + (g)     * 32 + k0 + 8 + c), qhi[s][2], qlo[s][2]);
        split2(*(const float2*)(qrow + (g + 8) * 32 + k0 + 8 + c), qhi[s][3], qlo[s][3]);
    }

    const float* trow  = tri + (size_t)h * 65536 + (size_t)(rowbase + g) * 256;
    const float* trow8 = trow + 8 * 256;

    __syncthreads();

    float acc[4][4];
    #pragma unroll
    for (int dn = 0; dn < 4; dn++)
        #pragma unroll
        for (int j = 0; j < 4; j++) acc[dn][j] = 0.f;
    float sum_g = 0.f, sum_h = 0.f;

    // ---- prefetch tile 0 triangle bias ----
    float2 tA = *(const float2*)(trow  + c);
    float2 tB = *(const float2*)(trow  + 8 + c);
    float2 tC = *(const float2*)(trow8 + c);
    float2 tD = *(const float2*)(trow8 + 8 + c);

    // ================= main loop over 16-key tiles =================
    #pragma unroll 1
    for (int kt = 0; kt < 16; kt++) {
        const int n0 = kt * 16;

        // ---- prefetch next tile's triangle bias (clamped on last iter) ----
        const int n1 = (kt == 15) ? n0 : n0 + 16;
        float2 nA = *(const float2*)(trow  + n1 + c);
        float2 nB = *(const float2*)(trow  + n1 + 8 + c);
        float2 nC = *(const float2*)(trow8 + n1 + c);
        float2 nD = *(const float2*)(trow8 + n1 + 8 + c);

        // ---- K fragment loads (scalar LDS, conflict-free) ----
        const char* kA = smem + (n0 + g)     * 80 + tg * 4;
        const char* kB = smem + (n0 + 8 + g) * 80 + tg * 4;
        uint32_t bAh[4], bAl[4], bBh[4], bBl[4];
        #pragma unroll
        for (int s = 0; s < 2; s++) {
            bAh[2*s]   = *(const uint32_t*)(kA + OFF_KH + s * 32);
            bAh[2*s+1] = *(const uint32_t*)(kA + OFF_KH + s * 32 + 16);
            bAl[2*s]   = *(const uint32_t*)(kA + OFF_KL + s * 32);
            bAl[2*s+1] = *(const uint32_t*)(kA + OFF_KL + s * 32 + 16);
            bBh[2*s]   = *(const uint32_t*)(kB + OFF_KH + s * 32);
            bBh[2*s+1] = *(const uint32_t*)(kB + OFF_KH + s * 32 + 16);
            bBl[2*s]   = *(const uint32_t*)(kB + OFF_KL + s * 32);
            bBl[2*s+1] = *(const uint32_t*)(kB + OFF_KL + s * 32 + 16);
        }

        // ---- QK^T: 4 independent accumulator chains (depth 3 each) ----
        float d0a[4] = {0.f,0.f,0.f,0.f}, d0b[4] = {0.f,0.f,0.f,0.f};
        float d1a[4] = {0.f,0.f,0.f,0.f}, d1b[4] = {0.f,0.f,0.f,0.f};
        mma16816(d0a, qhi[0], bAh[0], bAh[1]);
        mma16816(d1a, qhi[0], bBh[0], bBh[1]);
        mma16816(d0b, qhi[1], bAh[2], bAh[3]);
        mma16816(d1b, qhi[1], bBh[2], bBh[3]);
        mma16816(d0a, qhi[0], bAl[0], bAl[1]);
        mma16816(d1a, qhi[0], bBl[0], bBl[1]);
        mma16816(d0b, qhi[1], bAl[2], bAl[3]);
        mma16816(d1b, qhi[1], bBl[2], bBl[3]);
        mma16816(d0a, qlo[0], bAh[0], bAh[1]);
        mma16816(d1a, qlo[0], bBh[0], bBh[1]);
        mma16816(d0b, qlo[1], bAh[2], bAh[3]);
        mma16816(d1b, qlo[1], bBh[2], bBh[3]);

        // merge k-step partials
        float d0[4], d1[4];
        #pragma unroll
        for (int j = 0; j < 4; j++) { d0[j] = d0a[j] + d0b[j]; d1[j] = d1a[j] + d1b[j]; }

        // ---- bias + exp2 (no max subtraction; fp32-safe) ----
        float2 msA = *(const float2*)(smem + OFF_MS + (n0 + c) * 4);
        float2 msB = *(const float2*)(smem + OFF_MS + (n0 + 8 + c) * 4);
        float e00 = ex2f(fmaf(d0[0], C1, fmaf(tA.x, LOG2E, msA.x)));
        float e01 = ex2f(fmaf(d0[1], C1, fmaf(tA.y, LOG2E, msA.y)));
        float e02 = ex2f(fmaf(d0[2], C1, fmaf(tC.x, LOG2E, msA.x)));
        float e03 = ex2f(fmaf(d0[3], C1, fmaf(tC.y, LOG2E, msA.y)));
        float e10 = ex2f(fmaf(d1[0], C1, fmaf(tB.x, LOG2E, msB.x)));
        float e11 = ex2f(fmaf(d1[1], C1, fmaf(tB.y, LOG2E, msB.y)));
        float e12 = ex2f(fmaf(d1[2], C1, fmaf(tD.x, LOG2E, msB.x)));
        float e13 = ex2f(fmaf(d1[3], C1, fmaf(tD.y, LOG2E, msB.y)));
        sum_g += (e00 + e01) + (e10 + e11);
        sum_h += (e02 + e03) + (e12 + e13);

        // rotate prefetched bias into place
        tA = nA; tB = nB; tC = nC; tD = nD;

        // ---- P fragments (D-frag layout == A-frag layout) ----
        uint32_t ph[4], pl[4];
        { float2 x;
          x.x = e00; x.y = e01; split2(x, ph[0], pl[0]);
          x.x = e02; x.y = e03; split2(x, ph[1], pl[1]);
          x.x = e10; x.y = e11; split2(x, ph[2], pl[2]);
          x.x = e12; x.y = e13; split2(x, ph[3], pl[3]); }

        // ---- PV: out[16 x 32] += P[16 x 16] * V[16keys x 32] ----
        #pragma unroll
        for (int dn = 0; dn < 4; dn++) {
            const char* vrow = smem + (dn * 8 + g) * 528 + n0 * 2 + tg * 4;
            uint32_t vh0 = *(const uint32_t*)(vrow + OFF_VH);
            uint32_t vh1 = *(const uint32_t*)(vrow + OFF_VH + 16);
            uint32_t vl0 = *(const uint32_t*)(vrow + OFF_VL);
            uint32_t vl1 = *(const uint32_t*)(vrow + OFF_VL + 16);
            mma16816(acc[dn], ph, vh0, vh1);
            mma16816(acc[dn], ph, vl0, vl1);
            mma16816(acc[dn], pl, vh0, vh1);
        }
    }

    // ---- row-sum reduce within quad ----
    sum_g += __shfl_xor_sync(0xffffffffu, sum_g, 1);
    sum_g += __shfl_xor_sync(0xffffffffu, sum_g, 2);
    sum_h += __shfl_xor_sync(0xffffffffu, sum_h, 1);
    sum_h += __shfl_xor_sync(0xffffffffu, sum_h, 2);
    const float rg = 1.f / sum_g;
    const float rh = 1.f / sum_h;

    // ---- store ----
    float* orow = out + (size_t)head * 8192 + (size_t)rowbase * 32;
    #pragma unroll
    for (int dn = 0; dn < 4; dn++) {
        float2 w0 = {acc[dn][0] * rg, acc[dn][1] * rg};
        float2 w1 = {acc[dn][2] * rh, acc[dn][3] * rh};
        *(float2*)(orow + (g)     * 32 + dn * 8 + c) = w0;
        *(float2*)(orow + (g + 8) * 32 + dn * 8 + c) = w1;
    }
}

extern "C" void kernel_launch(void* const* d_in, const int* in_sizes, int n_in,
                              void* d_out, int out_size) {
    const float* q    = (const float*)d_in[0];
    const float* k    = (const float*)d_in[1];
    const float* v    = (const float*)d_in[2];
    const float* mask = (const float*)d_in[3];
    const float* tri  = (const float*)d_in[4];
    float* out = (float*)d_out;

    cudaFuncSetAttribute(TFA_88089779241014_kernel,
                         cudaFuncAttributeMaxDynamicSharedMemorySize, SMEM_TOTAL);
    // 1024 heads x 2 query tiles of 128
    TFA_88089779241014_kernel<<<2048, 256, SMEM_TOTAL>>>(q, k, v, mask, tri, out);
}

// round 10
// speedup vs baseline: 1.2207x; 1.2207x over previous
#include <cuda_runtime.h>
#include <cuda_bf16.h>
#include <cstdint>

#define LOG2E 1.4426950408889634f
#define C1 (0.17677669529663687f * LOG2E)   // sm_scale * log2(e)

// smem layout (bytes) — R4 padded layout
#define OFF_MS 0                      // mask * log2e, 256 f32 (1024 B)
#define OFF_KH 1024                   // K hi bf16 [256][32], row stride 80 B
#define OFF_KL (OFF_KH + 256*80)      // K lo
#define OFF_VH (OFF_KL + 256*80)      // Vt hi bf16 [32][256], row stride 528 B
#define OFF_VL (OFF_VH + 32*528)      // Vt lo
#define SMEM_TOTAL (OFF_VL + 32*528)  // 75776 B

__device__ __forceinline__ float ex2f(float x) {
    float y; asm("ex2.approx.ftz.f32 %0, %1;" : "=f"(y) : "f"(x)); return y;
}
__device__ __forceinline__ uint32_t pack2(float a, float b) {
    __nv_bfloat162 t = __floats2bfloat162_rn(a, b);   // low half = a
    return *(uint32_t*)&t;
}
__device__ __forceinline__ void split2(float2 x, uint32_t& hi, uint32_t& lo) {
    __nv_bfloat162 hv = __floats2bfloat162_rn(x.x, x.y);
    float2 hf = __bfloat1622float2(hv);
    hi = *(uint32_t*)&hv;
    lo = pack2(x.x - hf.x, x.y - hf.y);
}
__device__ __forceinline__ void mma16816(float* d, const uint32_t* a,
                                         uint32_t b0, uint32_t b1) {
    asm volatile(
        "mma.sync.aligned.m16n8k16.row.col.f32.bf16.bf16.f32 "
        "{%0,%1,%2,%3}, {%4,%5,%6,%7}, {%8,%9}, {%0,%1,%2,%3};"
        : "+f"(d[0]), "+f"(d[1]), "+f"(d[2]), "+f"(d[3])
        : "r"(a[0]), "r"(a[1]), "r"(a[2]), "r"(a[3]), "r"(b0), "r"(b1));
}

__global__ __launch_bounds__(256, 3)
void TFA_88089779241014_kernel(const float* __restrict__ q,
                               const float* __restrict__ k,
                               const float* __restrict__ v,
                               const float* __restrict__ mask,
                               const float* __restrict__ tri,
                               float* __restrict__ out) {
    extern __shared__ char smem[];

    const int tid  = threadIdx.x;
    const int lane = tid & 31;
    const int wid  = tid >> 5;
    const int g    = lane >> 2;
    const int c    = (lane & 3) * 2;
    const int tg   = lane & 3;

    const int bx   = blockIdx.x;        // head*2 + mtile
    const int head = bx >> 1;           // n*4 + h
    const int mt   = bx & 1;
    const int n    = head >> 2;
    const int h    = head & 3;

    const float* kb = k + (size_t)head * 8192;
    const float* vb = v + (size_t)head * 8192;
    const float* mb = mask + (size_t)n * 256;

    // ---- stage K as bf16 hi/lo, [t][d] rows, 80B stride ----
    for (int i = tid; i < 4096; i += 256) {
        int t = i >> 4, c2 = (i & 15) << 1;
        float2 x = *(const float2*)(kb + t * 32 + c2);
        uint32_t hi, lo; split2(x, hi, lo);
        *(uint32_t*)(smem + OFF_KH + t * 80 + c2 * 2) = hi;
        *(uint32_t*)(smem + OFF_KL + t * 80 + c2 * 2) = lo;
    }
    // ---- stage V transposed: Vt[d][t], 528B stride ----
    for (int i = tid; i < 2048; i += 256) {
        float4 x = ((const float4*)vb)[i];
        int t = i >> 3, d4 = (i & 7) << 2;
        float e[4] = {x.x, x.y, x.z, x.w};
        #pragma unroll
        for (int j = 0; j < 4; j++) {
            int d = d4 + j;
            __nv_bfloat16 hv = __float2bfloat16_rn(e[j]);
            __nv_bfloat16 lv = __float2bfloat16_rn(e[j] - __bfloat162float(hv));
            *(__nv_bfloat16*)(smem + OFF_VH + d * 528 + t * 2) = hv;
            *(__nv_bfloat16*)(smem + OFF_VL + d * 528 + t * 2) = lv;
        }
    }
    for (int i = tid; i < 256; i += 256)
        *(float*)(smem + OFF_MS + i * 4) = mb[i] * LOG2E;

    // ---- Q fragments (registers, whole kernel) ----
    const int rowbase = mt * 128 + wid * 16;
    const float* qrow = q + (size_t)head * 8192 + (size_t)rowbase * 32;
    uint32_t qhi[2][4], qlo[2][4];
    #pragma unroll
    for (int s = 0; s < 2; s++) {
        int k0 = s * 16;
        split2(*(const float2*)(qrow + (g)     * 32 + k0 + c),     qhi[s][0], qlo[s][0]);
        split2(*(const float2*)(qrow + (g + 8) * 32 + k0 + c),     qhi[s][1], qlo[s][1]);
        split2(*(const float2*)(qrow + (g)     * 32 + k0 + 8 + c), qhi[s][2], qlo[s][2]);
        split2(*(const float2*)(qrow + (g + 8) * 32 + k0 + 8 + c), qhi[s][3], qlo[s][3]);
    }

    const float* trow  = tri + (size_t)h * 65536 + (size_t)(rowbase + g) * 256;
    const float* trow8 = trow + 8 * 256;

    __syncthreads();

    float acc[4][4];
    #pragma unroll
    for (int dn = 0; dn < 4; dn++)
        #pragma unroll
        for (int j = 0; j < 4; j++) acc[dn][j] = 0.f;
    float sum_g = 0.f, sum_h = 0.f;

    // ---- prefetch tile 0's triangle bias ----
    float2 tA = *(const float2*)(trow  + c);
    float2 tB = *(const float2*)(trow  + 8 + c);
    float2 tC = *(const float2*)(trow8 + c);
    float2 tD = *(const float2*)(trow8 + 8 + c);

    // ================= main loop over 16-key tiles =================
    #pragma unroll 1
    for (int kt = 0; kt < 16; kt++) {
        const int n0 = kt * 16;

        // ---- K fragment loads (scalar LDS, conflict-free) ----
        const char* kA = smem + (n0 + g)     * 80 + tg * 4;
        const char* kB = smem + (n0 + 8 + g) * 80 + tg * 4;
        uint32_t bAh[4], bAl[4], bBh[4], bBl[4];
        #pragma unroll
        for (int s = 0; s < 2; s++) {
            bAh[2*s]   = *(const uint32_t*)(kA + OFF_KH + s * 32);
            bAh[2*s+1] = *(const uint32_t*)(kA + OFF_KH + s * 32 + 16);
            bAl[2*s]   = *(const uint32_t*)(kA + OFF_KL + s * 32);
            bAl[2*s+1] = *(const uint32_t*)(kA + OFF_KL + s * 32 + 16);
            bBh[2*s]   = *(const uint32_t*)(kB + OFF_KH + s * 32);
            bBh[2*s+1] = *(const uint32_t*)(kB + OFF_KH + s * 32 + 16);
            bBl[2*s]   = *(const uint32_t*)(kB + OFF_KL + s * 32);
            bBl[2*s+1] = *(const uint32_t*)(kB + OFF_KL + s * 32 + 16);
        }

        // ---- QK^T: 2 accumulators, 6 MMAs each ----
        float d0[4] = {0.f, 0.f, 0.f, 0.f};
        float d1[4] = {0.f, 0.f, 0.f, 0.f};
        mma16816(d0, qhi[0], bAh[0], bAh[1]);
        mma16816(d1, qhi[0], bBh[0], bBh[1]);
        mma16816(d0, qhi[1], bAh[2], bAh[3]);
        mma16816(d1, qhi[1], bBh[2], bBh[3]);
        mma16816(d0, qhi[0], bAl[0], bAl[1]);
        mma16816(d1, qhi[0], bBl[0], bBl[1]);
        mma16816(d0, qhi[1], bAl[2], bAl[3]);
        mma16816(d1, qhi[1], bBl[2], bBl[3]);
        mma16816(d0, qlo[0], bAh[0], bAh[1]);
        mma16816(d1, qlo[0], bBh[0], bBh[1]);
        mma16816(d0, qlo[1], bAh[2], bAh[3]);
        mma16816(d1, qlo[1], bBh[2], bBh[3]);

        // ---- bias + exp2 (no max subtraction; fp32-safe) ----
        float2 msA = *(const float2*)(smem + OFF_MS + (n0 + c) * 4);
        float2 msB = *(const float2*)(smem + OFF_MS + (n0 + 8 + c) * 4);
        float e00 = ex2f(fmaf(d0[0], C1, fmaf(tA.x, LOG2E, msA.x)));
        float e01 = ex2f(fmaf(d0[1], C1, fmaf(tA.y, LOG2E, msA.y)));
        float e02 = ex2f(fmaf(d0[2], C1, fmaf(tC.x, LOG2E, msA.x)));
        float e03 = ex2f(fmaf(d0[3], C1, fmaf(tC.y, LOG2E, msA.y)));
        float e10 = ex2f(fmaf(d1[0], C1, fmaf(tB.x, LOG2E, msB.x)));
        float e11 = ex2f(fmaf(d1[1], C1, fmaf(tB.y, LOG2E, msB.y)));
        float e12 = ex2f(fmaf(d1[2], C1, fmaf(tD.x, LOG2E, msB.x)));
        float e13 = ex2f(fmaf(d1[3], C1, fmaf(tD.y, LOG2E, msB.y)));
        sum_g += (e00 + e01) + (e10 + e11);
        sum_h += (e02 + e03) + (e12 + e13);

        // ---- prefetch NEXT tile's triangle bias (tA..tD just died, so the
        //      incoming values can reuse the same registers: ~zero reg cost;
        //      consumed next iteration, ~full tile of MMA work away) ----
        {
            const int n1 = (kt == 15) ? n0 : n0 + 16;
            tA = *(const float2*)(trow  + n1 + c);
            tB = *(const float2*)(trow  + n1 + 8 + c);
            tC = *(const float2*)(trow8 + n1 + c);
            tD = *(const float2*)(trow8 + n1 + 8 + c);
        }

        // ---- P fragments (D-frag layout == A-frag layout) ----
        uint32_t ph[4], pl[4];
        { float2 x;
          x.x = e00; x.y = e01; split2(x, ph[0], pl[0]);
          x.x = e02; x.y = e03; split2(x, ph[1], pl[1]);
          x.x = e10; x.y = e11; split2(x, ph[2], pl[2]);
          x.x = e12; x.y = e13; split2(x, ph[3], pl[3]); }

        // ---- PV: out[16 x 32] += P[16 x 16] * V[16keys x 32] ----
        #pragma unroll
        for (int dn = 0; dn < 4; dn++) {
            const char* vrow = smem + (dn * 8 + g) * 528 + n0 * 2 + tg * 4;
            uint32_t vh0 = *(const uint32_t*)(vrow + OFF_VH);
            uint32_t vh1 = *(const uint32_t*)(vrow + OFF_VH + 16);
            uint32_t vl0 = *(const uint32_t*)(vrow + OFF_VL);
            uint32_t vl1 = *(const uint32_t*)(vrow + OFF_VL + 16);
            mma16816(acc[dn], ph, vh0, vh1);
            mma16816(acc[dn], ph, vl0, vl1);
            mma16816(acc[dn], pl, vh0, vh1);
        }
    }

    // ---- row-sum reduce within quad ----
    sum_g += __shfl_xor_sync(0xffffffffu, sum_g, 1);
    sum_g += __shfl_xor_sync(0xffffffffu, sum_g, 2);
    sum_h += __shfl_xor_sync(0xffffffffu, sum_h, 1);
    sum_h += __shfl_xor_sync(0xffffffffu, sum_h, 2);
    const float rg = 1.f / sum_g;
    const float rh = 1.f / sum_h;

    // ---- store ----
    float* orow = out + (size_t)head * 8192 + (size_t)rowbase * 32;
    #pragma unroll
    for (int dn = 0; dn < 4; dn++) {
        float2 w0 = {acc[dn][0] * rg, acc[dn][1] * rg};
        float2 w1 = {acc[dn][2] * rh, acc[dn][3] * rh};
        *(float2*)(orow + (g)     * 32 + dn * 8 + c) = w0;
        *(float2*)(orow + (g + 8) * 32 + dn * 8 + c) = w1;
    }
}

extern "C" void kernel_launch(void* const* d_in, const int* in_sizes, int n_in,
                              void* d_out, int out_size) {
    const float* q    = (const float*)d_in[0];
    const float* k    = (const float*)d_in[1];
    const float* v    = (const float*)d_in[2];
    const float* mask = (const float*)d_in[3];
    const float* tri  = (const float*)d_in[4];
    float* out = (float*)d_out;

    cudaFuncSetAttribute(TFA_88089779241014_kernel,
                         cudaFuncAttributeMaxDynamicSharedMemorySize, SMEM_TOTAL);
    // 1024 heads x 2 query tiles of 128
    TFA_88089779241014_kernel<<<2048, 256, SMEM_TOTAL>>>(q, k, v, mask, tri, out);
}

// round 11
// speedup vs baseline: 1.2427x; 1.0181x over previous
#include <cuda_runtime.h>
#include <cuda_bf16.h>
#include <cuda_fp16.h>
#include <cstdint>

#define LOG2E 1.4426950408889634f
#define C1 (0.17677669529663687f * LOG2E)   // sm_scale * log2(e)

// smem layout (bytes) — padded layout (R4/R9)
#define OFF_MS 0                      // mask * log2e, 256 f32 (1024 B)
#define OFF_KH 1024                   // K hi fp16 [256][32], row stride 80 B
#define OFF_KL (OFF_KH + 256*80)      // K lo
#define OFF_VH (OFF_KL + 256*80)      // Vt hi fp16 [32][256], row stride 528 B
#define OFF_VL (OFF_VH + 32*528)      // Vt lo
#define SMEM_TOTAL (OFF_VL + 32*528)  // 75776 B

__device__ __forceinline__ float ex2f(float x) {
    float y; asm("ex2.approx.ftz.f32 %0, %1;" : "=f"(y) : "f"(x)); return y;
}
__device__ __forceinline__ uint32_t packh2(float a, float b) {
    __half2 t = __floats2half2_rn(a, b);   // low half = a
    return *(uint32_t*)&t;
}
// fp16 split: x = hi + lo (hi = RN(x), lo = RN(x - hi))
__device__ __forceinline__ void splith2(float2 x, uint32_t& hi, uint32_t& lo) {
    __half2 hv = __floats2half2_rn(x.x, x.y);
    float2 hf = __half22float2(hv);
    hi = *(uint32_t*)&hv;
    lo = packh2(x.x - hf.x, x.y - hf.y);
}
__device__ __forceinline__ void mma16816(float* d, const uint32_t* a,
                                         uint32_t b0, uint32_t b1) {
    asm volatile(
        "mma.sync.aligned.m16n8k16.row.col.f32.f16.f16.f32 "
        "{%0,%1,%2,%3}, {%4,%5,%6,%7}, {%8,%9}, {%0,%1,%2,%3};"
        : "+f"(d[0]), "+f"(d[1]), "+f"(d[2]), "+f"(d[3])
        : "r"(a[0]), "r"(a[1]), "r"(a[2]), "r"(a[3]), "r"(b0), "r"(b1));
}

__global__ __launch_bounds__(256, 3)
void TFA_88089779241014_kernel(const float* __restrict__ q,
                               const float* __restrict__ k,
                               const float* __restrict__ v,
                               const float* __restrict__ mask,
                               const float* __restrict__ tri,
                               float* __restrict__ out) {
    extern __shared__ char smem[];

    const int tid  = threadIdx.x;
    const int lane = tid & 31;
    const int wid  = tid >> 5;
    const int g    = lane >> 2;
    const int c    = (lane & 3) * 2;
    const int tg   = lane & 3;

    const int bx   = blockIdx.x;        // head*2 + mtile
    const int head = bx >> 1;           // n*4 + h
    const int mt   = bx & 1;
    const int n    = head >> 2;
    const int h    = head & 3;

    const float* kb = k + (size_t)head * 8192;
    const float* vb = v + (size_t)head * 8192;
    const float* mb = mask + (size_t)n * 256;

    // ---- stage K as fp16 hi/lo, [t][d] rows, 80B stride ----
    for (int i = tid; i < 4096; i += 256) {
        int t = i >> 4, c2 = (i & 15) << 1;
        float2 x = *(const float2*)(kb + t * 32 + c2);
        uint32_t hi, lo; splith2(x, hi, lo);
        *(uint32_t*)(smem + OFF_KH + t * 80 + c2 * 2) = hi;
        *(uint32_t*)(smem + OFF_KL + t * 80 + c2 * 2) = lo;
    }
    // ---- stage V transposed: Vt[d][t] fp16 hi/lo, 528B stride ----
    for (int i = tid; i < 2048; i += 256) {
        float4 x = ((const float4*)vb)[i];
        int t = i >> 3, d4 = (i & 7) << 2;
        float e[4] = {x.x, x.y, x.z, x.w};
        #pragma unroll
        for (int j = 0; j < 4; j++) {
            int d = d4 + j;
            __half hv = __float2half_rn(e[j]);
            __half lv = __float2half_rn(e[j] - __half2float(hv));
            *(__half*)(smem + OFF_VH + d * 528 + t * 2) = hv;
            *(__half*)(smem + OFF_VL + d * 528 + t * 2) = lv;
        }
    }
    for (int i = tid; i < 256; i += 256)
        *(float*)(smem + OFF_MS + i * 4) = mb[i] * LOG2E;

    // ---- Q fragments, fp16 hi only (registers, whole kernel) ----
    const int rowbase = mt * 128 + wid * 16;
    const float* qrow = q + (size_t)head * 8192 + (size_t)rowbase * 32;
    uint32_t qh[2][4];
    #pragma unroll
    for (int s = 0; s < 2; s++) {
        int k0 = s * 16;
        float2 a0 = *(const float2*)(qrow + (g)     * 32 + k0 + c);
        float2 a1 = *(const float2*)(qrow + (g + 8) * 32 + k0 + c);
        float2 a2 = *(const float2*)(qrow + (g)     * 32 + k0 + 8 + c);
        float2 a3 = *(const float2*)(qrow + (g + 8) * 32 + k0 + 8 + c);
        qh[s][0] = packh2(a0.x, a0.y);
        qh[s][1] = packh2(a1.x, a1.y);
        qh[s][2] = packh2(a2.x, a2.y);
        qh[s][3] = packh2(a3.x, a3.y);
    }

    const float* trow  = tri + (size_t)h * 65536 + (size_t)(rowbase + g) * 256;
    const float* trow8 = trow + 8 * 256;

    __syncthreads();

    float acc[4][4];
    #pragma unroll
    for (int dn = 0; dn < 4; dn++)
        #pragma unroll
        for (int j = 0; j < 4; j++) acc[dn][j] = 0.f;
    float sum_g = 0.f, sum_h = 0.f;

    // ---- prefetch tile 0's triangle bias ----
    float2 tA = *(const float2*)(trow  + c);
    float2 tB = *(const float2*)(trow  + 8 + c);
    float2 tC = *(const float2*)(trow8 + c);
    float2 tD = *(const float2*)(trow8 + 8 + c);

    // ================= main loop over 16-key tiles =================
    #pragma unroll 1
    for (int kt = 0; kt < 16; kt++) {
        const int n0 = kt * 16;

        // ---- K fragment loads (scalar LDS, conflict-free) ----
        const char* kA = smem + (n0 + g)     * 80 + tg * 4;
        const char* kB = smem + (n0 + 8 + g) * 80 + tg * 4;
        uint32_t bAh[4], bAl[4], bBh[4], bBl[4];
        #pragma unroll
        for (int s = 0; s < 2; s++) {
            bAh[2*s]   = *(const uint32_t*)(kA + OFF_KH + s * 32);
            bAh[2*s+1] = *(const uint32_t*)(kA + OFF_KH + s * 32 + 16);
            bAl[2*s]   = *(const uint32_t*)(kA + OFF_KL + s * 32);
            bAl[2*s+1] = *(const uint32_t*)(kA + OFF_KL + s * 32 + 16);
            bBh[2*s]   = *(const uint32_t*)(kB + OFF_KH + s * 32);
            bBh[2*s+1] = *(const uint32_t*)(kB + OFF_KH + s * 32 + 16);
            bBl[2*s]   = *(const uint32_t*)(kB + OFF_KL + s * 32);
            bBl[2*s+1] = *(const uint32_t*)(kB + OFF_KL + s * 32 + 16);
        }

        // ---- QK^T: fp16 2-product (qh·kh + qh·kl), 8 MMAs ----
        float d0[4] = {0.f, 0.f, 0.f, 0.f};
        float d1[4] = {0.f, 0.f, 0.f, 0.f};
        mma16816(d0, qh[0], bAh[0], bAh[1]);
        mma16816(d1, qh[0], bBh[0], bBh[1]);
        mma16816(d0, qh[1], bAh[2], bAh[3]);
        mma16816(d1, qh[1], bBh[2], bBh[3]);
        mma16816(d0, qh[0], bAl[0], bAl[1]);
        mma16816(d1, qh[0], bBl[0], bBl[1]);
        mma16816(d0, qh[1], bAl[2], bAl[3]);
        mma16816(d1, qh[1], bBl[2], bBl[3]);

        // ---- bias + exp2 (no max subtraction; fp32-safe) ----
        float2 msA = *(const float2*)(smem + OFF_MS + (n0 + c) * 4);
        float2 msB = *(const float2*)(smem + OFF_MS + (n0 + 8 + c) * 4);
        float e00 = ex2f(fmaf(d0[0], C1, fmaf(tA.x, LOG2E, msA.x)));
        float e01 = ex2f(fmaf(d0[1], C1, fmaf(tA.y, LOG2E, msA.y)));
        float e02 = ex2f(fmaf(d0[2], C1, fmaf(tC.x, LOG2E, msA.x)));
        float e03 = ex2f(fmaf(d0[3], C1, fmaf(tC.y, LOG2E, msA.y)));
        float e10 = ex2f(fmaf(d1[0], C1, fmaf(tB.x, LOG2E, msB.x)));
        float e11 = ex2f(fmaf(d1[1], C1, fmaf(tB.y, LOG2E, msB.y)));
        float e12 = ex2f(fmaf(d1[2], C1, fmaf(tD.x, LOG2E, msB.x)));
        float e13 = ex2f(fmaf(d1[3], C1, fmaf(tD.y, LOG2E, msB.y)));
        sum_g += (e00 + e01) + (e10 + e11);
        sum_h += (e02 + e03) + (e12 + e13);

        // ---- prefetch NEXT tile's triangle bias (zero-reg-cost placement) ----
        {
            const int n1 = (kt == 15) ? n0 : n0 + 16;
            tA = *(const float2*)(trow  + n1 + c);
            tB = *(const float2*)(trow  + n1 + 8 + c);
            tC = *(const float2*)(trow8 + n1 + c);
            tD = *(const float2*)(trow8 + n1 + 8 + c);
        }

        // ---- P fragments: fp16 hi only (D-frag layout == A-frag layout) ----
        uint32_t ph[4];
        ph[0] = packh2(e00, e01);
        ph[1] = packh2(e02, e03);
        ph[2] = packh2(e10, e11);
        ph[3] = packh2(e12, e13);

        // ---- PV: fp16 2-product (ph·vh + ph·vl), 8 MMAs ----
        #pragma unroll
        for (int dn = 0; dn < 4; dn++) {
            const char* vrow = smem + (dn * 8 + g) * 528 + n0 * 2 + tg * 4;
            uint32_t vh0 = *(const uint32_t*)(vrow + OFF_VH);
            uint32_t vh1 = *(const uint32_t*)(vrow + OFF_VH + 16);
            uint32_t vl0 = *(const uint32_t*)(vrow + OFF_VL);
            uint32_t vl1 = *(const uint32_t*)(vrow + OFF_VL + 16);
            mma16816(acc[dn], ph, vh0, vh1);
            mma16816(acc[dn], ph, vl0, vl1);
        }
    }

    // ---- row-sum reduce within quad ----
    sum_g += __shfl_xor_sync(0xffffffffu, sum_g, 1);
    sum_g += __shfl_xor_sync(0xffffffffu, sum_g, 2);
    sum_h += __shfl_xor_sync(0xffffffffu, sum_h, 1);
    sum_h += __shfl_xor_sync(0xffffffffu, sum_h, 2);
    const float rg = 1.f / sum_g;
    const float rh = 1.f / sum_h;

    // ---- store ----
    float* orow = out + (size_t)head * 8192 + (size_t)rowbase * 32;
    #pragma unroll
    for (int dn = 0; dn < 4; dn++) {
        float2 w0 = {acc[dn][0] * rg, acc[dn][1] * rg};
        float2 w1 = {acc[dn][2] * rh, acc[dn][3] * rh};
        *(float2*)(orow + (g)     * 32 + dn * 8 + c) = w0;
        *(float2*)(orow + (g + 8) * 32 + dn * 8 + c) = w1;
    }
}

extern "C" void kernel_launch(void* const* d_in, const int* in_sizes, int n_in,
                              void* d_out, int out_size) {
    const float* q    = (const float*)d_in[0];
    const float* k    = (const float*)d_in[1];
    const float* v    = (const float*)d_in[2];
    const float* mask = (const float*)d_in[3];
    const float* tri  = (const float*)d_in[4];
    float* out = (float*)d_out;

    cudaFuncSetAttribute(TFA_88089779241014_kernel,
                         cudaFuncAttributeMaxDynamicSharedMemorySize, SMEM_TOTAL);
    // 1024 heads x 2 query tiles of 128
    TFA_88089779241014_kernel<<<2048, 256, SMEM_TOTAL>>>(q, k, v, mask, tri, out);
}

// round 12
// speedup vs baseline: 1.4810x; 1.1917x over previous
#include <cuda_runtime.h>
#include <cuda_fp16.h>
#include <cstdint>

#define LOG2E 1.4426950408889634f
#define C1 (0.17677669529663687f * LOG2E)   // sm_scale * log2(e)

// smem layout (bytes) — padded layout
#define OFF_MS 0                      // mask * log2e, 256 f32 (1024 B)
#define OFF_KH 1024                   // K hi fp16 [256][32], row stride 80 B
#define OFF_KL (OFF_KH + 256*80)      // K lo
#define OFF_VH (OFF_KL + 256*80)      // Vt hi fp16 [32][256], row stride 528 B
#define OFF_VL (OFF_VH + 32*528)      // Vt lo
#define SMEM_TOTAL (OFF_VL + 32*528)  // 75776 B

__device__ __forceinline__ float ex2f(float x) {
    float y; asm("ex2.approx.ftz.f32 %0, %1;" : "=f"(y) : "f"(x)); return y;
}
__device__ __forceinline__ uint32_t packh2(float a, float b) {
    __half2 t = __floats2half2_rn(a, b);   // low half = a
    return *(uint32_t*)&t;
}
__device__ __forceinline__ void splith2(float2 x, uint32_t& hi, uint32_t& lo) {
    __half2 hv = __floats2half2_rn(x.x, x.y);
    float2 hf = __half22float2(hv);
    hi = *(uint32_t*)&hv;
    lo = packh2(x.x - hf.x, x.y - hf.y);
}
__device__ __forceinline__ void mma16816(float* d, const uint32_t* a,
                                         uint32_t b0, uint32_t b1) {
    asm volatile(
        "mma.sync.aligned.m16n8k16.row.col.f32.f16.f16.f32 "
        "{%0,%1,%2,%3}, {%4,%5,%6,%7}, {%8,%9}, {%0,%1,%2,%3};"
        : "+f"(d[0]), "+f"(d[1]), "+f"(d[2]), "+f"(d[3])
        : "r"(a[0]), "r"(a[1]), "r"(a[2]), "r"(a[3]), "r"(b0), "r"(b1));
}

__global__ __launch_bounds__(256, 2)
void TFA_88089779241014_kernel(const float* __restrict__ q,
                               const float* __restrict__ k,
                               const float* __restrict__ v,
                               const float* __restrict__ mask,
                               const float* __restrict__ tri,
                               float* __restrict__ out) {
    extern __shared__ char smem[];

    const int tid  = threadIdx.x;
    const int lane = tid & 31;
    const int wid  = tid >> 5;
    const int g    = lane >> 2;
    const int c    = (lane & 3) * 2;
    const int tg   = lane & 3;

    const int head = blockIdx.x;        // n*4 + h : one CTA per full head
    const int n    = head >> 2;
    const int h    = head & 3;

    const float* kb = k + (size_t)head * 8192;
    const float* vb = v + (size_t)head * 8192;
    const float* mb = mask + (size_t)n * 256;

    // ---- stage K as fp16 hi/lo, [t][d] rows, 80B stride ----
    for (int i = tid; i < 4096; i += 256) {
        int t = i >> 4, c2 = (i & 15) << 1;
        float2 x = *(const float2*)(kb + t * 32 + c2);
        uint32_t hi, lo; splith2(x, hi, lo);
        *(uint32_t*)(smem + OFF_KH + t * 80 + c2 * 2) = hi;
        *(uint32_t*)(smem + OFF_KL + t * 80 + c2 * 2) = lo;
    }
    // ---- stage V transposed: Vt[d][t] fp16 hi/lo, 528B stride ----
    for (int i = tid; i < 2048; i += 256) {
        float4 x = ((const float4*)vb)[i];
        int t = i >> 3, d4 = (i & 7) << 2;
        float e[4] = {x.x, x.y, x.z, x.w};
        #pragma unroll
        for (int j = 0; j < 4; j++) {
            int d = d4 + j;
            __half hv = __float2half_rn(e[j]);
            __half lv = __float2half_rn(e[j] - __half2float(hv));
            *(__half*)(smem + OFF_VH + d * 528 + t * 2) = hv;
            *(__half*)(smem + OFF_VL + d * 528 + t * 2) = lv;
        }
    }
    for (int i = tid; i < 256; i += 256)
        *(float*)(smem + OFF_MS + i * 4) = mb[i] * LOG2E;

    // ---- Q fragments: warp owns 32 rows = two 16-row A-tiles (fp16 hi only) ----
    const int rowbase = wid * 32;
    const float* qrow = q + (size_t)head * 8192 + (size_t)rowbase * 32;
    uint32_t qh0[2][4], qh1[2][4];
    #pragma unroll
    for (int s = 0; s < 2; s++) {
        int k0 = s * 16;
        #pragma unroll
        for (int m = 0; m < 2; m++) {
            const float* qm = qrow + m * 16 * 32;
            float2 a0 = *(const float2*)(qm + (g)     * 32 + k0 + c);
            float2 a1 = *(const float2*)(qm + (g + 8) * 32 + k0 + c);
            float2 a2 = *(const float2*)(qm + (g)     * 32 + k0 + 8 + c);
            float2 a3 = *(const float2*)(qm + (g + 8) * 32 + k0 + 8 + c);
            uint32_t* dst = m ? qh1[s] : qh0[s];
            dst[0] = packh2(a0.x, a0.y);
            dst[1] = packh2(a1.x, a1.y);
            dst[2] = packh2(a2.x, a2.y);
            dst[3] = packh2(a3.x, a3.y);
        }
    }

    const float* trow = tri + (size_t)h * 65536 + (size_t)(rowbase + g) * 256;

    __syncthreads();

    float acc0[4][4], acc1[4][4];
    #pragma unroll
    for (int dn = 0; dn < 4; dn++)
        #pragma unroll
        for (int j = 0; j < 4; j++) { acc0[dn][j] = 0.f; acc1[dn][j] = 0.f; }
    float s0g = 0.f, s0h = 0.f, s1g = 0.f, s1h = 0.f;

    // ================= main loop over 16-key tiles =================
    #pragma unroll 1
    for (int kt = 0; kt < 16; kt++) {
        const int n0 = kt * 16;

        // ---- K fragment loads (scalar LDS, conflict-free; shared by both m-tiles) ----
        const char* kA = smem + (n0 + g)     * 80 + tg * 4;
        const char* kB = smem + (n0 + 8 + g) * 80 + tg * 4;
        uint32_t bAh[4], bAl[4], bBh[4], bBl[4];
        #pragma unroll
        for (int s = 0; s < 2; s++) {
            bAh[2*s]   = *(const uint32_t*)(kA + OFF_KH + s * 32);
            bAh[2*s+1] = *(const uint32_t*)(kA + OFF_KH + s * 32 + 16);
            bAl[2*s]   = *(const uint32_t*)(kA + OFF_KL + s * 32);
            bAl[2*s+1] = *(const uint32_t*)(kA + OFF_KL + s * 32 + 16);
            bBh[2*s]   = *(const uint32_t*)(kB + OFF_KH + s * 32);
            bBh[2*s+1] = *(const uint32_t*)(kB + OFF_KH + s * 32 + 16);
            bBl[2*s]   = *(const uint32_t*)(kB + OFF_KL + s * 32);
            bBl[2*s+1] = *(const uint32_t*)(kB + OFF_KL + s * 32 + 16);
        }

        // ---- QK^T: fp16 2-product, both m-tiles on the same B-frags (16 MMAs) ----
        float d00[4] = {0.f,0.f,0.f,0.f}, d01[4] = {0.f,0.f,0.f,0.f};
        float d10[4] = {0.f,0.f,0.f,0.f}, d11[4] = {0.f,0.f,0.f,0.f};
        mma16816(d00, qh0[0], bAh[0], bAh[1]);
        mma16816(d01, qh0[0], bBh[0], bBh[1]);
        mma16816(d10, qh1[0], bAh[0], bAh[1]);
        mma16816(d11, qh1[0], bBh[0], bBh[1]);
        mma16816(d00, qh0[1], bAh[2], bAh[3]);
        mma16816(d01, qh0[1], bBh[2], bBh[3]);
        mma16816(d10, qh1[1], bAh[2], bAh[3]);
        mma16816(d11, qh1[1], bBh[2], bBh[3]);
        mma16816(d00, qh0[0], bAl[0], bAl[1]);
        mma16816(d01, qh0[0], bBl[0], bBl[1]);
        mma16816(d10, qh1[0], bAl[0], bAl[1]);
        mma16816(d11, qh1[0], bBl[0], bBl[1]);
        mma16816(d00, qh0[1], bAl[2], bAl[3]);
        mma16816(d01, qh0[1], bBl[2], bBl[3]);
        mma16816(d10, qh1[1], bAl[2], bAl[3]);
        mma16816(d11, qh1[1], bBl[2], bBl[3]);

        // ---- bias + exp2 (no max subtraction; fp32-safe) ----
        float2 msA = *(const float2*)(smem + OFF_MS + (n0 + c) * 4);
        float2 msB = *(const float2*)(smem + OFF_MS + (n0 + 8 + c) * 4);

        // m-tile 0: rows g, g+8
        float2 tA = *(const float2*)(trow             + n0 + c);
        float2 tB = *(const float2*)(trow             + n0 + 8 + c);
        float2 tC = *(const float2*)(trow + 8 * 256   + n0 + c);
        float2 tD = *(const float2*)(trow + 8 * 256   + n0 + 8 + c);
        float e00 = ex2f(fmaf(d00[0], C1, fmaf(tA.x, LOG2E, msA.x)));
        float e01 = ex2f(fmaf(d00[1], C1, fmaf(tA.y, LOG2E, msA.y)));
        float e02 = ex2f(fmaf(d00[2], C1, fmaf(tC.x, LOG2E, msA.x)));
        float e03 = ex2f(fmaf(d00[3], C1, fmaf(tC.y, LOG2E, msA.y)));
        float e10 = ex2f(fmaf(d01[0], C1, fmaf(tB.x, LOG2E, msB.x)));
        float e11 = ex2f(fmaf(d01[1], C1, fmaf(tB.y, LOG2E, msB.y)));
        float e12 = ex2f(fmaf(d01[2], C1, fmaf(tD.x, LOG2E, msB.x)));
        float e13 = ex2f(fmaf(d01[3], C1, fmaf(tD.y, LOG2E, msB.y)));
        s0g += (e00 + e01) + (e10 + e11);
        s0h += (e02 + e03) + (e12 + e13);
        uint32_t ph0[4];
        ph0[0] = packh2(e00, e01);
        ph0[1] = packh2(e02, e03);
        ph0[2] = packh2(e10, e11);
        ph0[3] = packh2(e12, e13);

        // m-tile 1: rows g+16, g+24
        tA = *(const float2*)(trow + 16 * 256 + n0 + c);
        tB = *(const float2*)(trow + 16 * 256 + n0 + 8 + c);
        tC = *(const float2*)(trow + 24 * 256 + n0 + c);
        tD = *(const float2*)(trow + 24 * 256 + n0 + 8 + c);
        e00 = ex2f(fmaf(d10[0], C1, fmaf(tA.x, LOG2E, msA.x)));
        e01 = ex2f(fmaf(d10[1], C1, fmaf(tA.y, LOG2E, msA.y)));
        e02 = ex2f(fmaf(d10[2], C1, fmaf(tC.x, LOG2E, msA.x)));
        e03 = ex2f(fmaf(d10[3], C1, fmaf(tC.y, LOG2E, msA.y)));
        e10 = ex2f(fmaf(d11[0], C1, fmaf(tB.x, LOG2E, msB.x)));
        e11 = ex2f(fmaf(d11[1], C1, fmaf(tB.y, LOG2E, msB.y)));
        e12 = ex2f(fmaf(d11[2], C1, fmaf(tD.x, LOG2E, msB.x)));
        e13 = ex2f(fmaf(d11[3], C1, fmaf(tD.y, LOG2E, msB.y)));
        s1g += (e00 + e01) + (e10 + e11);
        s1h += (e02 + e03) + (e12 + e13);
        uint32_t ph1[4];
        ph1[0] = packh2(e00, e01);
        ph1[1] = packh2(e02, e03);
        ph1[2] = packh2(e10, e11);
        ph1[3] = packh2(e12, e13);

        // ---- PV: fp16 2-product, both m-tiles on the same V-frags (16 MMAs) ----
        #pragma unroll
        for (int dn = 0; dn < 4; dn++) {
            const char* vrow = smem + (dn * 8 + g) * 528 + n0 * 2 + tg * 4;
            uint32_t vh0 = *(const uint32_t*)(vrow + OFF_VH);
            uint32_t vh1 = *(const uint32_t*)(vrow + OFF_VH + 16);
            uint32_t vl0 = *(const uint32_t*)(vrow + OFF_VL);
            uint32_t vl1 = *(const uint32_t*)(vrow + OFF_VL + 16);
            mma16816(acc0[dn], ph0, vh0, vh1);
            mma16816(acc1[dn], ph1, vh0, vh1);
            mma16816(acc0[dn], ph0, vl0, vl1);
            mma16816(acc1[dn], ph1, vl0, vl1);
        }
    }

    // ---- row-sum reduce within quad ----
    s0g += __shfl_xor_sync(0xffffffffu, s0g, 1);
    s0g += __shfl_xor_sync(0xffffffffu, s0g, 2);
    s0h += __shfl_xor_sync(0xffffffffu, s0h, 1);
    s0h += __shfl_xor_sync(0xffffffffu, s0h, 2);
    s1g += __shfl_xor_sync(0xffffffffu, s1g, 1);
    s1g += __shfl_xor_sync(0xffffffffu, s1g, 2);
    s1h += __shfl_xor_sync(0xffffffffu, s1h, 1);
    s1h += __shfl_xor_sync(0xffffffffu, s1h, 2);
    const float r0g = 1.f / s0g, r0h = 1.f / s0h;
    const float r1g = 1.f / s1g, r1h = 1.f / s1h;

    // ---- store (rows rowbase + g + {0,8,16,24}) ----
    float* orow = out + (size_t)head * 8192 + (size_t)rowbase * 32;
    #pragma unroll
    for (int dn = 0; dn < 4; dn++) {
        float2 w;
        w.x = acc0[dn][0] * r0g; w.y = acc0[dn][1] * r0g;
        *(float2*)(orow + (g)      * 32 + dn * 8 + c) = w;
        w.x = acc0[dn][2] * r0h; w.y = acc0[dn][3] * r0h;
        *(float2*)(orow + (g + 8)  * 32 + dn * 8 + c) = w;
        w.x = acc1[dn][0] * r1g; w.y = acc1[dn][1] * r1g;
        *(float2*)(orow + (g + 16) * 32 + dn * 8 + c) = w;
        w.x = acc1[dn][2] * r1h; w.y = acc1[dn][3] * r1h;
        *(float2*)(orow + (g + 24) * 32 + dn * 8 + c) = w;
    }
}

extern "C" void kernel_launch(void* const* d_in, const int* in_sizes, int n_in,
                              void* d_out, int out_size) {
    const float* q    = (const float*)d_in[0];
    const float* k    = (const float*)d_in[1];
    const float* v    = (const float*)d_in[2];
    const float* mask = (const float*)d_in[3];
    const float* tri  = (const float*)d_in[4];
    float* out = (float*)d_out;

    cudaFuncSetAttribute(TFA_88089779241014_kernel,
                         cudaFuncAttributeMaxDynamicSharedMemorySize, SMEM_TOTAL);
    // one CTA per head: 1024 CTAs
    TFA_88089779241014_kernel<<<1024, 256, SMEM_TOTAL>>>(q, k, v, mask, tri, out);
}